// round 11
// baseline (speedup 1.0000x reference)
#include <cuda_runtime.h>
#include <cuda_bf16.h>
#include <cstddef>

// ---------------------------------------------------------------------------
// GRU (B=64, N=1024, T=512), exact fp32, packed f32x2 FMA.
//
// Phase 1:  XP = x @ [W1|W2] + [b1|b2] — cp.async double-buffered SGEMM
//           (unchanged, ~1.25x FMA floor).
// Phase 2:  ONE persistent kernel, 128 blocks, W resident in smem (96 KB).
//           NEW: h broadcast pipelined via 3-slot cp.async ring (8 chunks of
//           32 k per step, chunk c+2 in flight while chunk c computes) ->
//           the 32 MB/step L2 broadcast + load latency hide under the FMA
//           shadow; one __syncthreads per chunk.
// ---------------------------------------------------------------------------

#define Bsz 64
#define Nn  1024
#define Tt  512
#define N3  3072
#define Kd  1024
#define NB  128

typedef unsigned long long ull;

__device__ __forceinline__ ull pk2(float lo, float hi) {
    ull r; asm("mov.b64 %0, {%1,%2};" : "=l"(r) : "f"(lo), "f"(hi)); return r;
}
__device__ __forceinline__ void upk2(ull v, float& lo, float& hi) {
    asm("mov.b64 {%0,%1}, %2;" : "=f"(lo), "=f"(hi) : "l"(v));
}
__device__ __forceinline__ void ffma2(ull& d, ull a, ull b) {
    asm("fma.rn.f32x2 %0, %1, %2, %0;" : "+l"(d) : "l"(a), "l"(b));
}
__device__ __forceinline__ void cp16(void* s, const void* g) {
    unsigned sa = (unsigned)__cvta_generic_to_shared(s);
    asm volatile("cp.async.ca.shared.global [%0], [%1], 16;" :: "r"(sa), "l"(g));
}
__device__ __forceinline__ void cp_commit() {
    asm volatile("cp.async.commit_group;");
}
template <int N>
__device__ __forceinline__ void cp_wait() {
    asm volatile("cp.async.wait_group %0;" :: "n"(N));
}

// ------------------------- device scratch ----------------------------------
__device__ float g_XP[(size_t)Bsz * Tt * N3];    // 402 MB input projections
__device__ float g_Ht[2][(size_t)Nn * Bsz];      // h, TRANSPOSED [k][m]

__device__ volatile unsigned g_bar_gen;
__device__ unsigned g_bar_cnt;

__global__ void init_state() {
    int i = blockIdx.x * 256 + threadIdx.x;
    if (i < Nn * Bsz) g_Ht[0][i] = 0.f;
    if (i == 0) { g_bar_cnt = 0; g_bar_gen = 0; }
}

// ------------------------- phase 1: input projection (unchanged) ------------
__global__ __launch_bounds__(256, 2) void xproj(
        const float* __restrict__ fx,
        const float* __restrict__ W1, const float* __restrict__ W2,
        const float* __restrict__ b1, const float* __restrict__ b2) {
    __shared__ float As[2][16][128];
    __shared__ float Bs[2][16][128];

    const int tid = threadIdx.x;
    const int jb  = blockIdx.x * 128;
    const int m0  = blockIdx.y * 128;
    const int b   = m0 >> 9;
    const int t0  = m0 & 511;
    const float* Abase = fx + ((size_t)b * Kd) * Tt + t0;

    const float* Bsrc;
    size_t bstride;
    if (jb < 2048) { Bsrc = W1 + jb;          bstride = 2048; }
    else           { Bsrc = W2 + (jb - 2048); bstride = 1024; }

    const int lm = tid & 31;
    const int lk = tid >> 5;
    const int ty = tid >> 4, tx = tid & 15;

    auto issue = [&](int k0, int nb) {
        int k1 = k0 + lk, k2 = k0 + lk + 8;
        cp16(&As[nb][lk][lm * 4],     Abase + (size_t)k1 * Tt + lm * 4);
        cp16(&As[nb][lk + 8][lm * 4], Abase + (size_t)k2 * Tt + lm * 4);
        cp16(&Bs[nb][lk][lm * 4],     Bsrc + (size_t)k1 * bstride + lm * 4);
        cp16(&Bs[nb][lk + 8][lm * 4], Bsrc + (size_t)k2 * bstride + lm * 4);
        cp_commit();
    };

    ull acc[8][4];
#pragma unroll
    for (int r = 0; r < 8; r++)
#pragma unroll
        for (int c = 0; c < 4; c++) acc[r][c] = 0ull;

    issue(0, 0);
    int buf = 0;
    for (int k0 = 0; k0 < Kd; k0 += 16) {
        const bool more = (k0 + 16 < Kd);
        if (more) { issue(k0 + 16, buf ^ 1); cp_wait<1>(); }
        else      { cp_wait<0>(); }
        __syncthreads();

#pragma unroll
        for (int q = 0; q < 16; q++) {
            const float4 a0 = *(const float4*)&As[buf][q][ty * 8];
            const float4 a1 = *(const float4*)&As[buf][q][ty * 8 + 4];
            const ull* bv = (const ull*)&Bs[buf][q][tx * 8];
            const ull b0 = bv[0], b1v = bv[1], b2v = bv[2], b3v = bv[3];
            float arow[8] = {a0.x, a0.y, a0.z, a0.w, a1.x, a1.y, a1.z, a1.w};
#pragma unroll
            for (int r = 0; r < 8; r++) {
                ull aa = pk2(arow[r], arow[r]);
                ffma2(acc[r][0], aa, b0);
                ffma2(acc[r][1], aa, b1v);
                ffma2(acc[r][2], aa, b2v);
                ffma2(acc[r][3], aa, b3v);
            }
        }
        __syncthreads();
        buf ^= 1;
    }

    float bb[8];
#pragma unroll
    for (int c = 0; c < 8; c++) {
        int j = jb + tx * 8 + c;
        bb[c] = (j < 2048) ? b1[j] : b2[j - 2048];
    }

#pragma unroll
    for (int r = 0; r < 8; r++) {
        float* op = g_XP + (size_t)(m0 + ty * 8 + r) * N3 + jb + tx * 8;
        float4 v0, v1;
        upk2(acc[r][0], v0.x, v0.y); upk2(acc[r][1], v0.z, v0.w);
        upk2(acc[r][2], v1.x, v1.y); upk2(acc[r][3], v1.z, v1.w);
        v0.x += bb[0]; v0.y += bb[1]; v0.z += bb[2]; v0.w += bb[3];
        v1.x += bb[4]; v1.y += bb[5]; v1.z += bb[6]; v1.w += bb[7];
        *(float4*)&op[0] = v0;
        *(float4*)&op[4] = v1;
    }
}

// ------------------------- phase 2: persistent recurrence -------------------
// smem (floats):
//   w_s  [1024][24]            98304 B  resident W slice
//   hT_s [3][4][32][64]        98304 B  3-slot cp.async ring of h chunks
//   p_s  [4][64][26]           26624 B  in-block K-split partials
//   bias [24]
#define SM_W    (1024 * 24)
#define SM_HT1  (4 * 32 * 64)          // one ring slot (8192 floats)
#define SM_P    (4 * 64 * 26)
#define SM_TOT  ((SM_W + 3 * SM_HT1 + SM_P + 24) * 4)

__device__ __forceinline__ void grid_sync() {
    __syncthreads();
    if (threadIdx.x == 0) {
        unsigned gen = g_bar_gen;
        __threadfence();
        if (atomicAdd(&g_bar_cnt, 1u) == NB - 1) {
            g_bar_cnt = 0;
            __threadfence();
            g_bar_gen = gen + 1;
        } else {
            while (g_bar_gen == gen) { __nanosleep(32); }
        }
        __threadfence();
    }
    __syncthreads();
}

__global__ __launch_bounds__(256, 1) void recurrence(
        const float* __restrict__ W1, const float* __restrict__ W2,
        const float* __restrict__ b1, const float* __restrict__ b2,
        float* __restrict__ out) {
    extern __shared__ float smem[];
    float* w_s    = smem;                    // [k][24]
    float* hT_s   = w_s + SM_W;              // [slot][g][32][64]
    float* p_s    = hT_s + 3 * SM_HT1;       // [g][64][26]
    float* bias_s = p_s + SM_P;              // [24]

    const int tid = threadIdx.x;
    const int blk = blockIdx.x;
    const int gc0 = blk * 8;
    const int grp = tid >> 6;                // k-split group 0..3
    const int gt  = tid & 63;
    const int rowg = gt >> 2;                // 16 row groups of 4
    const int cg   = gt & 3;                 // 4 col groups of 6

    // ---- resident W slice + biases ----------------------------------------
#pragma unroll
    for (int j = 0; j < 24; j++) {
        int l = tid + j * 256;
        int k = l / 6, f = l - k * 6;
        int p = f >> 1, half = f & 1;
        const float* src = (p == 0) ? (W1 + (size_t)k * 2048 + gc0 + half * 4)
                         : (p == 1) ? (W1 + (size_t)k * 2048 + 1024 + gc0 + half * 4)
                                    : (W2 + (size_t)k * 1024 + gc0 + half * 4);
        *(float4*)&w_s[k * 24 + p * 8 + half * 4] = *(const float4*)src;
    }
    if (tid < 24) {
        int p = tid >> 3, ii = tid & 7, n = gc0 + ii;
        bias_s[tid] = (p == 0) ? b1[n] : (p == 1) ? b1[1024 + n] : b2[n];
    }
    __syncthreads();

    // per-thread decomposition of one h chunk load (2048 float4, 8/thread)
    const int ld_m4 = tid & 15;              // within-row float4
    const int ld_kl = (tid >> 4) & 15;       // base kl (2 rows per j-pair)

    for (int t = 0; t < Tt; t++) {
        const float* hcur = g_Ht[t & 1];
        float*       hnxt = g_Ht[(t + 1) & 1];

        // issue one 32-k chunk into ring slot s (8 cp.async per thread)
        auto issue = [&](int c, int s) {
            float* dst = hT_s + s * SM_HT1;
#pragma unroll
            for (int j = 0; j < 8; j++) {
                int l = tid + j * 256;                 // 0..2047
                int m4 = l & 15, kl = (l >> 4) & 31, g = l >> 9;
                cp16(&dst[(g * 32 + kl) * 64 + m4 * 4],
                     &hcur[(g * 256 + c * 32 + kl) * 64 + m4 * 4]);
            }
            cp_commit();
        };

        // ---- prefetch gating inputs (LDG, consumed after the GEMM) --------
        float xq[2][3], hp[2];
#pragma unroll
        for (int e = 0; e < 2; e++) {
            int idx = tid + e * 256;
            int m = idx & 63, i = idx >> 6;
            int n = gc0 + i;
            const float* xp = g_XP + ((size_t)(m * Tt + t)) * N3 + n;
            xq[e][0] = xp[0];
            xq[e][1] = xp[1024];
            xq[e][2] = xp[2048];
            hp[e]    = hcur[n * 64 + m];
        }

        ull acc[4][3];
#pragma unroll
        for (int i = 0; i < 4; i++) { acc[i][0] = 0; acc[i][1] = 0; acc[i][2] = 0; }

        issue(0, 0);
        issue(1, 1);

#pragma unroll 1
        for (int c = 0; c < 8; c++) {
            if (c == 7) cp_wait<0>(); else cp_wait<1>();
            __syncthreads();
            if (c + 2 < 8) issue(c + 2, (c + 2) % 3);

            const float* hg = hT_s + (c % 3) * SM_HT1 + grp * (32 * 64);
            const float* wb = w_s + (grp * 256 + c * 32) * 24;
#pragma unroll 8
            for (int kk = 0; kk < 32; kk++) {
                float4 hv = *(const float4*)&hg[kk * 64 + rowg * 4];
                const ull* wv = (const ull*)&wb[kk * 24 + cg * 6];
                const ull w0 = wv[0], w1 = wv[1], w2 = wv[2];
                float arv[4] = {hv.x, hv.y, hv.z, hv.w};
#pragma unroll
                for (int i = 0; i < 4; i++) {
                    ull aa = pk2(arv[i], arv[i]);
                    ffma2(acc[i][0], aa, w0);
                    ffma2(acc[i][1], aa, w1);
                    ffma2(acc[i][2], aa, w2);
                }
            }
        }

        // ---- in-block partials, reduce, gate, update ----------------------
#pragma unroll
        for (int i = 0; i < 4; i++) {
            ull* pp = (ull*)&p_s[(grp * 64 + rowg * 4 + i) * 26 + cg * 6];
            pp[0] = acc[i][0]; pp[1] = acc[i][1]; pp[2] = acc[i][2];
        }
        __syncthreads();

#pragma unroll
        for (int e = 0; e < 2; e++) {
            int idx = tid + e * 256;
            int m = idx & 63, i = idx >> 6;
            int n = gc0 + i;
            float s1 = 0.f, s2 = 0.f, sh = 0.f;
#pragma unroll
            for (int g = 0; g < 4; g++) {
                const float* pp = &p_s[(g * 64 + m) * 26];
                s1 += pp[i]; s2 += pp[8 + i]; sh += pp[16 + i];
            }
            // reference adds biases in BOTH x-proj and h-proj — replicate
            float z = 1.f / (1.f + expf(-(xq[e][0] + s1 + bias_s[i])));
            float r = 1.f / (1.f + expf(-(xq[e][1] + s2 + bias_s[8 + i])));
            float hrec = sh + bias_s[16 + i];
            float hn = z * hp[e] + (1.f - z) * tanhf(xq[e][2] + r * hrec);
            hnxt[n * 64 + m] = hn;
            if (t == Tt - 1) out[m * Nn + n] = hn;
        }

        __threadfence();
        grid_sync();
    }
}

// ---------------------------------------------------------------------------
extern "C" void kernel_launch(void* const* d_in, const int* in_sizes, int n_in,
                              void* d_out, int out_size) {
    const float *fx = nullptr, *W1 = nullptr, *b1 = nullptr, *W2 = nullptr, *b2 = nullptr;
    for (int i = 0; i < n_in; i++) {
        switch (in_sizes[i]) {
            case Bsz * Nn * Tt:  fx = (const float*)d_in[i]; break;
            case Nn * 2 * Nn:    W1 = (const float*)d_in[i]; break;
            case 2 * Nn:         b1 = (const float*)d_in[i]; break;
            case Nn * Nn:        W2 = (const float*)d_in[i]; break;
            case Nn:             b2 = (const float*)d_in[i]; break;
            default: break;
        }
    }
    float* out = (float*)d_out;

    static int smem_set = 0;
    if (!smem_set) {
        cudaFuncSetAttribute(recurrence, cudaFuncAttributeMaxDynamicSharedMemorySize,
                             SM_TOT);
        smem_set = 1;
    }

    init_state<<<(Nn * Bsz + 255) / 256, 256>>>();

    dim3 g1(N3 / 128, (Bsz * Tt) / 128);   // (24, 256)
    xproj<<<g1, 256>>>(fx, W1, W2, b1, b2);

    recurrence<<<NB, 256, SM_TOT>>>(W1, W2, b1, b2, out);
}

// round 12
// speedup vs baseline: 1.0058x; 1.0058x over previous
#include <cuda_runtime.h>
#include <cuda_bf16.h>
#include <cstddef>

// ---------------------------------------------------------------------------
// GRU (B=64, N=1024, T=512), exact fp32, packed f32x2 FMA.
//
// Phase 1:  XP = x @ [W1|W2] + [b1|b2] — cp.async double-buffered SGEMM.
// Phase 2:  ONE persistent kernel, 128 blocks x 512 threads (16 warps, 4 per
//           SMSP): W slice resident in smem, 8-way in-block K-split, 4 h-tile
//           chunks per step (load->sync->compute), block-local reduce + gates,
//           one grid barrier per step.
// ---------------------------------------------------------------------------

#define Bsz 64
#define Nn  1024
#define Tt  512
#define N3  3072
#define Kd  1024
#define NB  128

typedef unsigned long long ull;

__device__ __forceinline__ ull pk2(float lo, float hi) {
    ull r; asm("mov.b64 %0, {%1,%2};" : "=l"(r) : "f"(lo), "f"(hi)); return r;
}
__device__ __forceinline__ void upk2(ull v, float& lo, float& hi) {
    asm("mov.b64 {%0,%1}, %2;" : "=f"(lo), "=f"(hi) : "l"(v));
}
__device__ __forceinline__ void ffma2(ull& d, ull a, ull b) {
    asm("fma.rn.f32x2 %0, %1, %2, %0;" : "+l"(d) : "l"(a), "l"(b));
}
__device__ __forceinline__ void cp16(void* s, const void* g) {
    unsigned sa = (unsigned)__cvta_generic_to_shared(s);
    asm volatile("cp.async.ca.shared.global [%0], [%1], 16;" :: "r"(sa), "l"(g));
}
__device__ __forceinline__ void cp_commit() {
    asm volatile("cp.async.commit_group;");
}
template <int N>
__device__ __forceinline__ void cp_wait() {
    asm volatile("cp.async.wait_group %0;" :: "n"(N));
}

// ------------------------- device scratch ----------------------------------
__device__ float g_XP[(size_t)Bsz * Tt * N3];    // 402 MB input projections
__device__ float g_Ht[2][(size_t)Nn * Bsz];      // h, TRANSPOSED [k][m]

__device__ volatile unsigned g_bar_gen;
__device__ unsigned g_bar_cnt;

__global__ void init_state() {
    int i = blockIdx.x * 256 + threadIdx.x;
    if (i < Nn * Bsz) g_Ht[0][i] = 0.f;
    if (i == 0) { g_bar_cnt = 0; g_bar_gen = 0; }
}

// ------------------------- phase 1: input projection (unchanged) ------------
__global__ __launch_bounds__(256, 2) void xproj(
        const float* __restrict__ fx,
        const float* __restrict__ W1, const float* __restrict__ W2,
        const float* __restrict__ b1, const float* __restrict__ b2) {
    __shared__ float As[2][16][128];
    __shared__ float Bs[2][16][128];

    const int tid = threadIdx.x;
    const int jb  = blockIdx.x * 128;
    const int m0  = blockIdx.y * 128;
    const int b   = m0 >> 9;
    const int t0  = m0 & 511;
    const float* Abase = fx + ((size_t)b * Kd) * Tt + t0;

    const float* Bsrc;
    size_t bstride;
    if (jb < 2048) { Bsrc = W1 + jb;          bstride = 2048; }
    else           { Bsrc = W2 + (jb - 2048); bstride = 1024; }

    const int lm = tid & 31;
    const int lk = tid >> 5;
    const int ty = tid >> 4, tx = tid & 15;

    auto issue = [&](int k0, int nb) {
        int k1 = k0 + lk, k2 = k0 + lk + 8;
        cp16(&As[nb][lk][lm * 4],     Abase + (size_t)k1 * Tt + lm * 4);
        cp16(&As[nb][lk + 8][lm * 4], Abase + (size_t)k2 * Tt + lm * 4);
        cp16(&Bs[nb][lk][lm * 4],     Bsrc + (size_t)k1 * bstride + lm * 4);
        cp16(&Bs[nb][lk + 8][lm * 4], Bsrc + (size_t)k2 * bstride + lm * 4);
        cp_commit();
    };

    ull acc[8][4];
#pragma unroll
    for (int r = 0; r < 8; r++)
#pragma unroll
        for (int c = 0; c < 4; c++) acc[r][c] = 0ull;

    issue(0, 0);
    int buf = 0;
    for (int k0 = 0; k0 < Kd; k0 += 16) {
        const bool more = (k0 + 16 < Kd);
        if (more) { issue(k0 + 16, buf ^ 1); cp_wait<1>(); }
        else      { cp_wait<0>(); }
        __syncthreads();

#pragma unroll
        for (int q = 0; q < 16; q++) {
            const float4 a0 = *(const float4*)&As[buf][q][ty * 8];
            const float4 a1 = *(const float4*)&As[buf][q][ty * 8 + 4];
            const ull* bv = (const ull*)&Bs[buf][q][tx * 8];
            const ull b0 = bv[0], b1v = bv[1], b2v = bv[2], b3v = bv[3];
            float arow[8] = {a0.x, a0.y, a0.z, a0.w, a1.x, a1.y, a1.z, a1.w};
#pragma unroll
            for (int r = 0; r < 8; r++) {
                ull aa = pk2(arow[r], arow[r]);
                ffma2(acc[r][0], aa, b0);
                ffma2(acc[r][1], aa, b1v);
                ffma2(acc[r][2], aa, b2v);
                ffma2(acc[r][3], aa, b3v);
            }
        }
        __syncthreads();
        buf ^= 1;
    }

    float bb[8];
#pragma unroll
    for (int c = 0; c < 8; c++) {
        int j = jb + tx * 8 + c;
        bb[c] = (j < 2048) ? b1[j] : b2[j - 2048];
    }

#pragma unroll
    for (int r = 0; r < 8; r++) {
        float* op = g_XP + (size_t)(m0 + ty * 8 + r) * N3 + jb + tx * 8;
        float4 v0, v1;
        upk2(acc[r][0], v0.x, v0.y); upk2(acc[r][1], v0.z, v0.w);
        upk2(acc[r][2], v1.x, v1.y); upk2(acc[r][3], v1.z, v1.w);
        v0.x += bb[0]; v0.y += bb[1]; v0.z += bb[2]; v0.w += bb[3];
        v1.x += bb[4]; v1.y += bb[5]; v1.z += bb[6]; v1.w += bb[7];
        *(float4*)&op[0] = v0;
        *(float4*)&op[4] = v1;
    }
}

// ------------------------- phase 2: persistent recurrence -------------------
// 512 threads, 8 k-split groups of 64 threads (128 k each).
// smem (floats):
//   w_s  [1024][24]        98304 B  resident W slice
//   hT_s [8][32][64]       65536 B  h chunk (per-group 32-k sub-tile)
//   p_s  [8][64][26]       53248 B  in-block K-split partials
//   bias [24]
#define SM_W    (1024 * 24)
#define SM_HT   (8 * 32 * 64)
#define SM_P    (8 * 64 * 26)
#define SM_TOT  ((SM_W + SM_HT + SM_P + 24) * 4)

__device__ __forceinline__ void grid_sync() {
    __syncthreads();
    if (threadIdx.x == 0) {
        unsigned gen = g_bar_gen;
        __threadfence();
        if (atomicAdd(&g_bar_cnt, 1u) == NB - 1) {
            g_bar_cnt = 0;
            __threadfence();
            g_bar_gen = gen + 1;
        } else {
            while (g_bar_gen == gen) { __nanosleep(32); }
        }
        __threadfence();
    }
    __syncthreads();
}

__global__ __launch_bounds__(512, 1) void recurrence(
        const float* __restrict__ W1, const float* __restrict__ W2,
        const float* __restrict__ b1, const float* __restrict__ b2,
        float* __restrict__ out) {
    extern __shared__ float smem[];
    float* w_s    = smem;                 // [k][24]
    float* hT_s   = w_s + SM_W;           // [g][32][64]
    float* p_s    = hT_s + SM_HT;         // [g][64][26]
    float* bias_s = p_s + SM_P;           // [24]

    const int tid = threadIdx.x;
    const int blk = blockIdx.x;
    const int gc0 = blk * 8;              // 8 gate-cols per block
    const int grp = tid >> 6;             // k-split group 0..7 (128 k each)
    const int gt  = tid & 63;
    const int rowg = gt >> 2;             // 16 row groups of 4
    const int cg   = gt & 3;              // 4 col groups of 6

    // ---- resident W slice + biases ----------------------------------------
#pragma unroll
    for (int j = 0; j < 12; j++) {
        int l = tid + j * 512;            // 0..6143 float4s
        int k = l / 6, f = l - k * 6;
        int p = f >> 1, half = f & 1;
        const float* src = (p == 0) ? (W1 + (size_t)k * 2048 + gc0 + half * 4)
                         : (p == 1) ? (W1 + (size_t)k * 2048 + 1024 + gc0 + half * 4)
                                    : (W2 + (size_t)k * 1024 + gc0 + half * 4);
        *(float4*)&w_s[k * 24 + p * 8 + half * 4] = *(const float4*)src;
    }
    if (tid < 24) {
        int p = tid >> 3, ii = tid & 7, n = gc0 + ii;
        bias_s[tid] = (p == 0) ? b1[n] : (p == 1) ? b1[1024 + n] : b2[n];
    }
    __syncthreads();

    const int um = tid & 63;              // update-element row (batch)
    const int ui = tid >> 6;              // update-element gate-col 0..7
    const int un = gc0 + ui;

    for (int t = 0; t < Tt; t++) {
        const float* hcur = g_Ht[t & 1];
        float*       hnxt = g_Ht[(t + 1) & 1];

        // ---- prefetch gating inputs (1 element/thread) --------------------
        const float* xp = g_XP + ((size_t)(um * Tt + t)) * N3 + un;
        float x1 = xp[0], x2 = xp[1024], x3 = xp[2048];
        float hp = hcur[un * 64 + um];

        // ---- GEMM: 24 cols x 64 rows, full K, 8-way in-block K split ------
        ull acc[4][3];
#pragma unroll
        for (int i = 0; i < 4; i++) { acc[i][0] = 0; acc[i][1] = 0; acc[i][2] = 0; }

        for (int it = 0; it < 4; it++) {
            // coop load: per-group 32-k sub-chunk (4096 float4, 8/thread)
#pragma unroll
            for (int j = 0; j < 8; j++) {
                int l = tid + j * 512;            // 0..4095
                int m4 = l & 15, kl = (l >> 4) & 31, g = l >> 9;
                *(float4*)&hT_s[(g * 32 + kl) * 64 + m4 * 4] =
                    *(const float4*)&hcur[(g * 128 + it * 32 + kl) * 64 + m4 * 4];
            }
            __syncthreads();

            const float* hg = hT_s + grp * (32 * 64);
            const float* wb = w_s + (grp * 128 + it * 32) * 24;
#pragma unroll 8
            for (int kk = 0; kk < 32; kk++) {
                float4 hv = *(const float4*)&hg[kk * 64 + rowg * 4];
                const ull* wv = (const ull*)&wb[kk * 24 + cg * 6];
                const ull w0 = wv[0], w1 = wv[1], w2 = wv[2];
                float arv[4] = {hv.x, hv.y, hv.z, hv.w};
#pragma unroll
                for (int i = 0; i < 4; i++) {
                    ull aa = pk2(arv[i], arv[i]);
                    ffma2(acc[i][0], aa, w0);
                    ffma2(acc[i][1], aa, w1);
                    ffma2(acc[i][2], aa, w2);
                }
            }
            __syncthreads();
        }

        // ---- in-block partials --------------------------------------------
#pragma unroll
        for (int i = 0; i < 4; i++) {
            ull* pp = (ull*)&p_s[(grp * 64 + rowg * 4 + i) * 26 + cg * 6];
            pp[0] = acc[i][0]; pp[1] = acc[i][1]; pp[2] = acc[i][2];
        }
        __syncthreads();

        // ---- fused reduce + gates + h update (1 element/thread) -----------
        {
            float s1 = 0.f, s2 = 0.f, sh = 0.f;
#pragma unroll
            for (int g = 0; g < 8; g++) {
                const float* pp = &p_s[(g * 64 + um) * 26];
                s1 += pp[ui]; s2 += pp[8 + ui]; sh += pp[16 + ui];
            }
            // reference adds biases in BOTH x-proj and h-proj — replicate
            float z = 1.f / (1.f + expf(-(x1 + s1 + bias_s[ui])));
            float r = 1.f / (1.f + expf(-(x2 + s2 + bias_s[8 + ui])));
            float hrec = sh + bias_s[16 + ui];
            float hn = z * hp + (1.f - z) * tanhf(x3 + r * hrec);
            hnxt[un * 64 + um] = hn;
            if (t == Tt - 1) out[um * Nn + un] = hn;
        }

        __threadfence();
        grid_sync();
    }
}

// ---------------------------------------------------------------------------
extern "C" void kernel_launch(void* const* d_in, const int* in_sizes, int n_in,
                              void* d_out, int out_size) {
    const float *fx = nullptr, *W1 = nullptr, *b1 = nullptr, *W2 = nullptr, *b2 = nullptr;
    for (int i = 0; i < n_in; i++) {
        switch (in_sizes[i]) {
            case Bsz * Nn * Tt:  fx = (const float*)d_in[i]; break;
            case Nn * 2 * Nn:    W1 = (const float*)d_in[i]; break;
            case 2 * Nn:         b1 = (const float*)d_in[i]; break;
            case Nn * Nn:        W2 = (const float*)d_in[i]; break;
            case Nn:             b2 = (const float*)d_in[i]; break;
            default: break;
        }
    }
    float* out = (float*)d_out;

    static int smem_set = 0;
    if (!smem_set) {
        cudaFuncSetAttribute(recurrence, cudaFuncAttributeMaxDynamicSharedMemorySize,
                             SM_TOT);
        smem_set = 1;
    }

    init_state<<<(Nn * Bsz + 255) / 256, 256>>>();

    dim3 g1(N3 / 128, (Bsz * Tt) / 128);   // (24, 256)
    xproj<<<g1, 256>>>(fx, W1, W2, b1, b2);

    recurrence<<<NB, 512, SM_TOT>>>(W1, W2, b1, b2, out);
}

// round 14
// speedup vs baseline: 1.2735x; 1.2661x over previous
#include <cuda_runtime.h>
#include <cuda_bf16.h>
#include <cstdint>
#include <cstddef>

// ---------------------------------------------------------------------------
// GRU (B=64, N=1024, T=512).
//
// Phase 1:  XP = x @ [W1|W2] + [b1|b2] on the tensor pipe via mma.sync
//           (m16n8k16 bf16, compiles for compute_103 — tcgen05 does NOT).
//           bf16x3 split: Ah*Bh + Ah*Bl + Al*Bh, fp32 accumulate, each
//           partial product exact. Dropped Al*Bl ~ 4e-6 relative.
// Phase 2:  persistent recurrence (exact R8 design, best measured):
//           128 blocks, W resident in smem, transposed double-buffered h,
//           one grid barrier per step, packed f32x2 FMA.
// ---------------------------------------------------------------------------

#define Bsz 64
#define Nn  1024
#define Tt  512
#define N3  3072
#define Kd  1024
#define NB  128
#define Mrows (Bsz * Tt)   // 32768

typedef unsigned long long ull;

__device__ __forceinline__ ull pk2(float lo, float hi) {
    ull r; asm("mov.b64 %0, {%1,%2};" : "=l"(r) : "f"(lo), "f"(hi)); return r;
}
__device__ __forceinline__ void upk2(ull v, float& lo, float& hi) {
    asm("mov.b64 {%0,%1}, %2;" : "=f"(lo), "=f"(hi) : "l"(v));
}
__device__ __forceinline__ void ffma2(ull& d, ull a, ull b) {
    asm("fma.rn.f32x2 %0, %1, %2, %0;" : "+l"(d) : "l"(a), "l"(b));
}
__device__ __forceinline__ void cp16(void* s, const void* g) {
    unsigned sa = (unsigned)__cvta_generic_to_shared(s);
    asm volatile("cp.async.ca.shared.global [%0], [%1], 16;" :: "r"(sa), "l"(g));
}
__device__ __forceinline__ void cp_commit() { asm volatile("cp.async.commit_group;"); }
template <int N>
__device__ __forceinline__ void cp_wait() {
    asm volatile("cp.async.wait_group %0;" :: "n"(N));
}
__device__ __forceinline__ uint32_t smem_u32(const void* p) {
    return (uint32_t)__cvta_generic_to_shared(p);
}
__device__ __forceinline__ void ldsm4(uint32_t* r, uint32_t addr) {
    asm volatile("ldmatrix.sync.aligned.m8n8.x4.shared.b16 {%0,%1,%2,%3}, [%4];"
                 : "=r"(r[0]), "=r"(r[1]), "=r"(r[2]), "=r"(r[3]) : "r"(addr));
}
__device__ __forceinline__ void mma_bf16(float* c, const uint32_t* a, const uint32_t* b) {
    asm volatile(
        "mma.sync.aligned.m16n8k16.row.col.f32.bf16.bf16.f32 "
        "{%0,%1,%2,%3}, {%4,%5,%6,%7}, {%8,%9}, {%0,%1,%2,%3};"
        : "+f"(c[0]), "+f"(c[1]), "+f"(c[2]), "+f"(c[3])
        : "r"(a[0]), "r"(a[1]), "r"(a[2]), "r"(a[3]), "r"(b[0]), "r"(b[1]));
}

// ------------------------- device scratch ----------------------------------
__device__ float g_XP[(size_t)Mrows * N3];               // 402 MB
__device__ float g_Ht[2][(size_t)Nn * Bsz];              // h transposed [k][m]
__device__ __nv_bfloat16 g_Ahi[(size_t)Mrows * Kd];      // [m][k]
__device__ __nv_bfloat16 g_Alo[(size_t)Mrows * Kd];
__device__ __nv_bfloat16 g_Bhi[(size_t)N3 * Kd];         // [n][k] = W^T
__device__ __nv_bfloat16 g_Blo[(size_t)N3 * Kd];

__device__ volatile unsigned g_bar_gen;
__device__ unsigned g_bar_cnt;

__global__ void init_state() {
    int i = blockIdx.x * 256 + threadIdx.x;
    if (i < Nn * Bsz) g_Ht[0][i] = 0.f;
    if (i == 0) { g_bar_cnt = 0; g_bar_gen = 0; }
}

// ------------------------- converts ----------------------------------------
// A[m][k] = fx[b][k][t], m = b*512 + t;  hi/lo bf16 split.
__global__ void conv_a(const float* __restrict__ fx) {
    __shared__ float tile[32][33];
    int k0 = blockIdx.x * 32, t0 = blockIdx.y * 32, b = blockIdx.z;
    int tx = threadIdx.x & 31, ty = threadIdx.x >> 5;
#pragma unroll
    for (int i = 0; i < 4; i++)
        tile[ty + 8 * i][tx] = fx[((size_t)b * Kd + k0 + ty + 8 * i) * Tt + t0 + tx];
    __syncthreads();
#pragma unroll
    for (int i = 0; i < 4; i++) {
        float v = tile[tx][ty + 8 * i];
        __nv_bfloat16 hi = __float2bfloat16(v);
        __nv_bfloat16 lo = __float2bfloat16(v - __bfloat162float(hi));
        size_t idx = ((size_t)b * Tt + t0 + ty + 8 * i) * Kd + k0 + tx;
        g_Ahi[idx] = hi;
        g_Alo[idx] = lo;
    }
}

// B[n][k] = W[k][n]; n<2048 from W1, else W2.
__global__ void conv_w(const float* __restrict__ W1, const float* __restrict__ W2) {
    __shared__ float tile[32][33];
    int k0 = blockIdx.x * 32, n0 = blockIdx.y * 32;
    int tx = threadIdx.x & 31, ty = threadIdx.x >> 5;
    const float* src; int stride, nb;
    if (n0 < 2048) { src = W1; stride = 2048; nb = n0; }
    else           { src = W2; stride = 1024; nb = n0 - 2048; }
#pragma unroll
    for (int i = 0; i < 4; i++)
        tile[ty + 8 * i][tx] = src[(size_t)(k0 + ty + 8 * i) * stride + nb + tx];
    __syncthreads();
#pragma unroll
    for (int i = 0; i < 4; i++) {
        float v = tile[tx][ty + 8 * i];
        __nv_bfloat16 hi = __float2bfloat16(v);
        __nv_bfloat16 lo = __float2bfloat16(v - __bfloat162float(hi));
        size_t idx = (size_t)(n0 + ty + 8 * i) * Kd + k0 + tx;
        g_Bhi[idx] = hi;
        g_Blo[idx] = lo;
    }
}

// ------------------------- phase 1: mma.sync xproj --------------------------
// Block tile 128x128, 8 warps (4 along M x 2 along N), warp tile 32x64.
// K chunks of 32 bf16, cp.async double buffer.
// smem per buffer: Ahi|Alo|Bhi|Blo, each 128 rows x 40 bf16 (pad: 80B stride,
// conflict-free for ldmatrix). Buffer = 20480 elems (40960 B); x2 = 80 KB.
#define XR       40                  // padded row stride (bf16 elems)
#define XARR     (128 * XR)          // 5120 elems per array
#define XBUF     (4 * XARR)          // 20480 elems per buffer
#define XSMEM    (2 * XBUF * 2)      // bytes

__global__ __launch_bounds__(256, 2) void xproj_mma(
        const float* __restrict__ b1, const float* __restrict__ b2) {
    extern __shared__ __nv_bfloat16 xsm[];

    const int tid = threadIdx.x;
    const int wid = tid >> 5, lane = tid & 31;
    const int n0 = blockIdx.x * 128;
    const int m0 = blockIdx.y * 128;
    const int wm = (wid & 3) * 32;       // warp row base in tile
    const int wn = (wid >> 2) * 64;      // warp col base in tile

    auto issue = [&](int c, int buf) {
        __nv_bfloat16* base = xsm + buf * XBUF;
#pragma unroll
        for (int j = 0; j < 8; j++) {
            int l = tid + j * 256;           // 0..2047
            int arr = l >> 9;                // 0..3: Ahi, Alo, Bhi, Blo
            int r   = (l >> 2) & 127;
            int seg = l & 3;
            const __nv_bfloat16* gsrc;
            if (arr == 0)      gsrc = g_Ahi + (size_t)(m0 + r) * Kd + c * 32 + seg * 8;
            else if (arr == 1) gsrc = g_Alo + (size_t)(m0 + r) * Kd + c * 32 + seg * 8;
            else if (arr == 2) gsrc = g_Bhi + (size_t)(n0 + r) * Kd + c * 32 + seg * 8;
            else               gsrc = g_Blo + (size_t)(n0 + r) * Kd + c * 32 + seg * 8;
            cp16(base + arr * XARR + r * XR + seg * 8, gsrc);
        }
        cp_commit();
    };

    float acc[2][8][4];
#pragma unroll
    for (int mt = 0; mt < 2; mt++)
#pragma unroll
        for (int nt = 0; nt < 8; nt++)
#pragma unroll
            for (int i = 0; i < 4; i++) acc[mt][nt][i] = 0.f;

    issue(0, 0);
    int buf = 0;
    for (int c = 0; c < Kd / 32; c++) {
        const bool more = (c + 1 < Kd / 32);
        if (more) { issue(c + 1, buf ^ 1); cp_wait<1>(); }
        else      { cp_wait<0>(); }
        __syncthreads();

        __nv_bfloat16* bp = xsm + buf * XBUF;
        const int arow  = lane & 15;
        const int akoff = (lane >> 4) << 3;
        const int brow  = (lane & 7) + ((lane >> 4) << 3);
        const int bkoff = ((lane >> 3) & 1) << 3;

#pragma unroll
        for (int kk = 0; kk < 32; kk += 16) {
            uint32_t ah[2][4], al[2][4], bb[4][4];
#pragma unroll
            for (int mt = 0; mt < 2; mt++) {
                uint32_t ad = smem_u32(bp + (wm + mt * 16 + arow) * XR + kk + akoff);
                ldsm4(ah[mt], ad);
                ldsm4(al[mt], ad + XARR * 2);
            }
#pragma unroll
            for (int nt = 0; nt < 4; nt++) {
                uint32_t bd = smem_u32(bp + 2 * XARR + (wn + nt * 16 + brow) * XR + kk + bkoff);
                ldsm4(bb[nt], bd);
            }
#pragma unroll
            for (int mt = 0; mt < 2; mt++)
#pragma unroll
                for (int nt = 0; nt < 4; nt++) {
                    mma_bf16(acc[mt][nt * 2],     ah[mt], &bb[nt][0]);
                    mma_bf16(acc[mt][nt * 2 + 1], ah[mt], &bb[nt][2]);
                    mma_bf16(acc[mt][nt * 2],     al[mt], &bb[nt][0]);
                    mma_bf16(acc[mt][nt * 2 + 1], al[mt], &bb[nt][2]);
                }
#pragma unroll
            for (int nt = 0; nt < 4; nt++) {
                uint32_t bd = smem_u32(bp + 3 * XARR + (wn + nt * 16 + brow) * XR + kk + bkoff);
                ldsm4(bb[nt], bd);
            }
#pragma unroll
            for (int mt = 0; mt < 2; mt++)
#pragma unroll
                for (int nt = 0; nt < 4; nt++) {
                    mma_bf16(acc[mt][nt * 2],     ah[mt], &bb[nt][0]);
                    mma_bf16(acc[mt][nt * 2 + 1], ah[mt], &bb[nt][2]);
                }
        }
        __syncthreads();
        buf ^= 1;
    }

    // epilogue: + bias, store fp32
    const int g = lane >> 2, tig = lane & 3;
#pragma unroll
    for (int mt = 0; mt < 2; mt++) {
#pragma unroll
        for (int nt = 0; nt < 8; nt++) {
            int n = n0 + wn + nt * 8 + tig * 2;
            float bv0 = (n < 2048) ? b1[n] : b2[n - 2048];
            float bv1 = (n + 1 < 2048) ? b1[n + 1] : b2[n + 1 - 2048];
            int m = m0 + wm + mt * 16 + g;
            float2 v0 = {acc[mt][nt][0] + bv0, acc[mt][nt][1] + bv1};
            float2 v1 = {acc[mt][nt][2] + bv0, acc[mt][nt][3] + bv1};
            *(float2*)&g_XP[(size_t)m * N3 + n] = v0;
            *(float2*)&g_XP[(size_t)(m + 8) * N3 + n] = v1;
        }
    }
}

// ------------------------- phase 2: persistent recurrence (R8, unchanged) ---
#define SM_W   (1024 * 24)
#define SM_HT  (4 * 64 * 64)
#define SM_P   (4 * 64 * 26)
#define SM_TOT ((SM_W + SM_HT + SM_P + 24) * 4)

__device__ __forceinline__ void grid_sync() {
    __syncthreads();
    if (threadIdx.x == 0) {
        unsigned gen = g_bar_gen;
        __threadfence();
        if (atomicAdd(&g_bar_cnt, 1u) == NB - 1) {
            g_bar_cnt = 0;
            __threadfence();
            g_bar_gen = gen + 1;
        } else {
            while (g_bar_gen == gen) { __nanosleep(32); }
        }
        __threadfence();
    }
    __syncthreads();
}

__global__ __launch_bounds__(256, 1) void recurrence(
        const float* __restrict__ W1, const float* __restrict__ W2,
        const float* __restrict__ b1, const float* __restrict__ b2,
        float* __restrict__ out) {
    extern __shared__ float smem[];
    float* w_s    = smem;                 // [k][24]
    float* hT_s   = w_s + SM_W;           // [g][64][64]
    float* p_s    = hT_s + SM_HT;         // [g][64][26]
    float* bias_s = p_s + SM_P;           // [24]

    const int tid = threadIdx.x;
    const int blk = blockIdx.x;
    const int gc0 = blk * 8;
    const int grp = tid >> 6;
    const int gt  = tid & 63;
    const int rowg = gt >> 2;
    const int cg   = gt & 3;

#pragma unroll
    for (int j = 0; j < 24; j++) {
        int l = tid + j * 256;
        int k = l / 6, f = l - k * 6;
        int p = f >> 1, half = f & 1;
        const float* src = (p == 0) ? (W1 + (size_t)k * 2048 + gc0 + half * 4)
                         : (p == 1) ? (W1 + (size_t)k * 2048 + 1024 + gc0 + half * 4)
                                    : (W2 + (size_t)k * 1024 + gc0 + half * 4);
        *(float4*)&w_s[k * 24 + p * 8 + half * 4] = *(const float4*)src;
    }
    if (tid < 24) {
        int p = tid >> 3, ii = tid & 7, n = gc0 + ii;
        bias_s[tid] = (p == 0) ? b1[n] : (p == 1) ? b1[1024 + n] : b2[n];
    }
    __syncthreads();

    for (int t = 0; t < Tt; t++) {
        const float* hcur = g_Ht[t & 1];
        float*       hnxt = g_Ht[(t + 1) & 1];

        float xq[2][3], hp[2];
#pragma unroll
        for (int e = 0; e < 2; e++) {
            int idx = tid + e * 256;
            int m = idx & 63, i = idx >> 6;
            int n = gc0 + i;
            const float* xp = g_XP + ((size_t)(m * Tt + t)) * N3 + n;
            xq[e][0] = xp[0];
            xq[e][1] = xp[1024];
            xq[e][2] = xp[2048];
            hp[e]    = hcur[n * 64 + m];
        }

        ull acc[4][3];
#pragma unroll
        for (int i = 0; i < 4; i++) { acc[i][0] = 0; acc[i][1] = 0; acc[i][2] = 0; }

        for (int it = 0; it < 4; it++) {
#pragma unroll
            for (int j = 0; j < 16; j++) {
                int l = tid + j * 256;
                int m4 = l & 15, kl = (l >> 4) & 63, g = l >> 10;
                *(float4*)&hT_s[(g * 64 + kl) * 64 + m4 * 4] =
                    *(const float4*)&hcur[(g * 256 + it * 64 + kl) * 64 + m4 * 4];
            }
            __syncthreads();

            const float* hg = hT_s + grp * (64 * 64);
            const float* wb = w_s + (grp * 256 + it * 64) * 24;
#pragma unroll 8
            for (int kk = 0; kk < 64; kk++) {
                float4 hv = *(const float4*)&hg[kk * 64 + rowg * 4];
                const ull* wv = (const ull*)&wb[kk * 24 + cg * 6];
                const ull w0 = wv[0], w1 = wv[1], w2 = wv[2];
                float arv[4] = {hv.x, hv.y, hv.z, hv.w};
#pragma unroll
                for (int i = 0; i < 4; i++) {
                    ull aa = pk2(arv[i], arv[i]);
                    ffma2(acc[i][0], aa, w0);
                    ffma2(acc[i][1], aa, w1);
                    ffma2(acc[i][2], aa, w2);
                }
            }
            __syncthreads();
        }

#pragma unroll
        for (int i = 0; i < 4; i++) {
            ull* pp = (ull*)&p_s[(grp * 64 + rowg * 4 + i) * 26 + cg * 6];
            pp[0] = acc[i][0]; pp[1] = acc[i][1]; pp[2] = acc[i][2];
        }
        __syncthreads();

#pragma unroll
        for (int e = 0; e < 2; e++) {
            int idx = tid + e * 256;
            int m = idx & 63, i = idx >> 6;
            int n = gc0 + i;
            float s1 = 0.f, s2 = 0.f, sh = 0.f;
#pragma unroll
            for (int g = 0; g < 4; g++) {
                const float* pp = &p_s[(g * 64 + m) * 26];
                s1 += pp[i]; s2 += pp[8 + i]; sh += pp[16 + i];
            }
            float z = 1.f / (1.f + expf(-(xq[e][0] + s1 + bias_s[i])));
            float r = 1.f / (1.f + expf(-(xq[e][1] + s2 + bias_s[8 + i])));
            float hrec = sh + bias_s[16 + i];
            float hn = z * hp[e] + (1.f - z) * tanhf(xq[e][2] + r * hrec);
            hnxt[n * 64 + m] = hn;
            if (t == Tt - 1) out[m * Nn + n] = hn;
        }

        __threadfence();
        grid_sync();
    }
}

// ---------------------------------------------------------------------------
extern "C" void kernel_launch(void* const* d_in, const int* in_sizes, int n_in,
                              void* d_out, int out_size) {
    const float *fx = nullptr, *W1 = nullptr, *b1 = nullptr, *W2 = nullptr, *b2 = nullptr;
    for (int i = 0; i < n_in; i++) {
        switch (in_sizes[i]) {
            case Bsz * Nn * Tt:  fx = (const float*)d_in[i]; break;
            case Nn * 2 * Nn:    W1 = (const float*)d_in[i]; break;
            case 2 * Nn:         b1 = (const float*)d_in[i]; break;
            case Nn * Nn:        W2 = (const float*)d_in[i]; break;
            case Nn:             b2 = (const float*)d_in[i]; break;
            default: break;
        }
    }
    float* out = (float*)d_out;

    cudaFuncSetAttribute(recurrence, cudaFuncAttributeMaxDynamicSharedMemorySize, SM_TOT);
    cudaFuncSetAttribute(xproj_mma,  cudaFuncAttributeMaxDynamicSharedMemorySize, XSMEM);

    init_state<<<(Nn * Bsz + 255) / 256, 256>>>();

    conv_a<<<dim3(Kd / 32, Tt / 32, Bsz), 256>>>(fx);
    conv_w<<<dim3(Kd / 32, N3 / 32), 256>>>(W1, W2);

    xproj_mma<<<dim3(N3 / 128, Mrows / 128), 256, XSMEM>>>(b1, b2);

    recurrence<<<NB, 256, SM_TOT>>>(W1, W2, b1, b2, out);
}

// round 15
// speedup vs baseline: 1.4524x; 1.1405x over previous
#include <cuda_runtime.h>
#include <cuda_bf16.h>
#include <cstdint>
#include <cstddef>

// ---------------------------------------------------------------------------
// GRU (B=64, N=1024, T=512) — both GEMMs on the tensor pipe via mma.sync
// (m16n8k16 bf16, bf16x3 split: Ah*Bh + Al*Bh + Ah*Bl, fp32 accumulate).
//
// Phase 1:  XP = x @ [W1|W2] + [b1|b2]  (validated R13 kernel, 1.56 ms).
// Phase 2:  persistent kernel, 512 steps:
//   GEMM: 128 blocks = 64 n-tiles(48 cols) x 2 K-halves(512). B slice (bf16
//         hi/lo, from the same g_Bhi/g_Blo as phase 1) resident in smem;
//         h chunks (bf16 hi/lo, [m][k]) cp.async double-buffered; partials
//         to global. Update phase: reduce 2 partials + gates, writes h as
//         fp32 [n][m] AND bf16 hi/lo [m][k] for the next step's GEMM.
//   Two grid barriers per step.
// ---------------------------------------------------------------------------

#define Bsz 64
#define Nn  1024
#define Tt  512
#define N3  3072
#define Kd  1024
#define NB  128
#define Mrows (Bsz * Tt)   // 32768

typedef unsigned long long ull;

__device__ __forceinline__ void cp16(void* s, const void* g) {
    unsigned sa = (unsigned)__cvta_generic_to_shared(s);
    asm volatile("cp.async.ca.shared.global [%0], [%1], 16;" :: "r"(sa), "l"(g));
}
__device__ __forceinline__ void cp_commit() { asm volatile("cp.async.commit_group;"); }
template <int N>
__device__ __forceinline__ void cp_wait() {
    asm volatile("cp.async.wait_group %0;" :: "n"(N));
}
__device__ __forceinline__ uint32_t smem_u32(const void* p) {
    return (uint32_t)__cvta_generic_to_shared(p);
}
__device__ __forceinline__ void ldsm4(uint32_t* r, uint32_t addr) {
    asm volatile("ldmatrix.sync.aligned.m8n8.x4.shared.b16 {%0,%1,%2,%3}, [%4];"
                 : "=r"(r[0]), "=r"(r[1]), "=r"(r[2]), "=r"(r[3]) : "r"(addr));
}
__device__ __forceinline__ void ldsm2(uint32_t* r, uint32_t addr) {
    asm volatile("ldmatrix.sync.aligned.m8n8.x2.shared.b16 {%0,%1}, [%2];"
                 : "=r"(r[0]), "=r"(r[1]) : "r"(addr));
}
__device__ __forceinline__ void mma_bf16(float* c, const uint32_t* a, const uint32_t* b) {
    asm volatile(
        "mma.sync.aligned.m16n8k16.row.col.f32.bf16.bf16.f32 "
        "{%0,%1,%2,%3}, {%4,%5,%6,%7}, {%8,%9}, {%0,%1,%2,%3};"
        : "+f"(c[0]), "+f"(c[1]), "+f"(c[2]), "+f"(c[3])
        : "r"(a[0]), "r"(a[1]), "r"(a[2]), "r"(a[3]), "r"(b[0]), "r"(b[1]));
}

// ------------------------- device scratch ----------------------------------
__device__ float g_XP[(size_t)Mrows * N3];               // 402 MB
__device__ __nv_bfloat16 g_Ahi[(size_t)Mrows * Kd];      // [m][k]
__device__ __nv_bfloat16 g_Alo[(size_t)Mrows * Kd];
__device__ __nv_bfloat16 g_Bhi[(size_t)N3 * Kd];         // [n][k] = W^T (shared by both phases)
__device__ __nv_bfloat16 g_Blo[(size_t)N3 * Kd];
__device__ float g_Hf[Nn * Bsz];                         // fp32 h, [n][m]
__device__ __nv_bfloat16 g_Hhi[Bsz * Nn];                // bf16 h hi, [m][k]
__device__ __nv_bfloat16 g_Hlo[Bsz * Nn];                // bf16 h lo, [m][k]
__device__ float g_G[2 * Bsz * N3];                      // split-K partials

__device__ volatile unsigned g_bar_gen;
__device__ unsigned g_bar_cnt;

__global__ void init_state() {
    int i = blockIdx.x * 256 + threadIdx.x;
    if (i < Nn * Bsz) {
        g_Hf[i] = 0.f;
        g_Hhi[i] = __float2bfloat16(0.f);
        g_Hlo[i] = __float2bfloat16(0.f);
    }
    if (i == 0) { g_bar_cnt = 0; g_bar_gen = 0; }
}

// ------------------------- converts ----------------------------------------
__global__ void conv_a(const float* __restrict__ fx) {
    __shared__ float tile[32][33];
    int k0 = blockIdx.x * 32, t0 = blockIdx.y * 32, b = blockIdx.z;
    int tx = threadIdx.x & 31, ty = threadIdx.x >> 5;
#pragma unroll
    for (int i = 0; i < 4; i++)
        tile[ty + 8 * i][tx] = fx[((size_t)b * Kd + k0 + ty + 8 * i) * Tt + t0 + tx];
    __syncthreads();
#pragma unroll
    for (int i = 0; i < 4; i++) {
        float v = tile[tx][ty + 8 * i];
        __nv_bfloat16 hi = __float2bfloat16(v);
        __nv_bfloat16 lo = __float2bfloat16(v - __bfloat162float(hi));
        size_t idx = ((size_t)b * Tt + t0 + ty + 8 * i) * Kd + k0 + tx;
        g_Ahi[idx] = hi;
        g_Alo[idx] = lo;
    }
}

__global__ void conv_w(const float* __restrict__ W1, const float* __restrict__ W2) {
    __shared__ float tile[32][33];
    int k0 = blockIdx.x * 32, n0 = blockIdx.y * 32;
    int tx = threadIdx.x & 31, ty = threadIdx.x >> 5;
    const float* src; int stride, nb;
    if (n0 < 2048) { src = W1; stride = 2048; nb = n0; }
    else           { src = W2; stride = 1024; nb = n0 - 2048; }
#pragma unroll
    for (int i = 0; i < 4; i++)
        tile[ty + 8 * i][tx] = src[(size_t)(k0 + ty + 8 * i) * stride + nb + tx];
    __syncthreads();
#pragma unroll
    for (int i = 0; i < 4; i++) {
        float v = tile[tx][ty + 8 * i];
        __nv_bfloat16 hi = __float2bfloat16(v);
        __nv_bfloat16 lo = __float2bfloat16(v - __bfloat162float(hi));
        size_t idx = (size_t)(n0 + ty + 8 * i) * Kd + k0 + tx;
        g_Bhi[idx] = hi;
        g_Blo[idx] = lo;
    }
}

// ------------------------- phase 1: mma.sync xproj (R13, unchanged) ---------
#define XR       40
#define XARR     (128 * XR)
#define XBUF     (4 * XARR)
#define XSMEM    (2 * XBUF * 2)

__global__ __launch_bounds__(256, 2) void xproj_mma(
        const float* __restrict__ b1, const float* __restrict__ b2) {
    extern __shared__ __nv_bfloat16 xsm[];

    const int tid = threadIdx.x;
    const int wid = tid >> 5, lane = tid & 31;
    const int n0 = blockIdx.x * 128;
    const int m0 = blockIdx.y * 128;
    const int wm = (wid & 3) * 32;
    const int wn = (wid >> 2) * 64;

    auto issue = [&](int c, int buf) {
        __nv_bfloat16* base = xsm + buf * XBUF;
#pragma unroll
        for (int j = 0; j < 8; j++) {
            int l = tid + j * 256;
            int arr = l >> 9;
            int r   = (l >> 2) & 127;
            int seg = l & 3;
            const __nv_bfloat16* gsrc;
            if (arr == 0)      gsrc = g_Ahi + (size_t)(m0 + r) * Kd + c * 32 + seg * 8;
            else if (arr == 1) gsrc = g_Alo + (size_t)(m0 + r) * Kd + c * 32 + seg * 8;
            else if (arr == 2) gsrc = g_Bhi + (size_t)(n0 + r) * Kd + c * 32 + seg * 8;
            else               gsrc = g_Blo + (size_t)(n0 + r) * Kd + c * 32 + seg * 8;
            cp16(base + arr * XARR + r * XR + seg * 8, gsrc);
        }
        cp_commit();
    };

    float acc[2][8][4];
#pragma unroll
    for (int mt = 0; mt < 2; mt++)
#pragma unroll
        for (int nt = 0; nt < 8; nt++)
#pragma unroll
            for (int i = 0; i < 4; i++) acc[mt][nt][i] = 0.f;

    issue(0, 0);
    int buf = 0;
    for (int c = 0; c < Kd / 32; c++) {
        const bool more = (c + 1 < Kd / 32);
        if (more) { issue(c + 1, buf ^ 1); cp_wait<1>(); }
        else      { cp_wait<0>(); }
        __syncthreads();

        __nv_bfloat16* bp = xsm + buf * XBUF;
        const int arow  = lane & 15;
        const int akoff = (lane >> 4) << 3;
        const int brow  = (lane & 7) + ((lane >> 4) << 3);
        const int bkoff = ((lane >> 3) & 1) << 3;

#pragma unroll
        for (int kk = 0; kk < 32; kk += 16) {
            uint32_t ah[2][4], al[2][4], bb[4][4];
#pragma unroll
            for (int mt = 0; mt < 2; mt++) {
                uint32_t ad = smem_u32(bp + (wm + mt * 16 + arow) * XR + kk + akoff);
                ldsm4(ah[mt], ad);
                ldsm4(al[mt], ad + XARR * 2);
            }
#pragma unroll
            for (int nt = 0; nt < 4; nt++) {
                uint32_t bd = smem_u32(bp + 2 * XARR + (wn + nt * 16 + brow) * XR + kk + bkoff);
                ldsm4(bb[nt], bd);
            }
#pragma unroll
            for (int mt = 0; mt < 2; mt++)
#pragma unroll
                for (int nt = 0; nt < 4; nt++) {
                    mma_bf16(acc[mt][nt * 2],     ah[mt], &bb[nt][0]);
                    mma_bf16(acc[mt][nt * 2 + 1], ah[mt], &bb[nt][2]);
                    mma_bf16(acc[mt][nt * 2],     al[mt], &bb[nt][0]);
                    mma_bf16(acc[mt][nt * 2 + 1], al[mt], &bb[nt][2]);
                }
#pragma unroll
            for (int nt = 0; nt < 4; nt++) {
                uint32_t bd = smem_u32(bp + 3 * XARR + (wn + nt * 16 + brow) * XR + kk + bkoff);
                ldsm4(bb[nt], bd);
            }
#pragma unroll
            for (int mt = 0; mt < 2; mt++)
#pragma unroll
                for (int nt = 0; nt < 4; nt++) {
                    mma_bf16(acc[mt][nt * 2],     ah[mt], &bb[nt][0]);
                    mma_bf16(acc[mt][nt * 2 + 1], ah[mt], &bb[nt][2]);
                }
        }
        __syncthreads();
        buf ^= 1;
    }

    const int g = lane >> 2, tig = lane & 3;
#pragma unroll
    for (int mt = 0; mt < 2; mt++) {
#pragma unroll
        for (int nt = 0; nt < 8; nt++) {
            int n = n0 + wn + nt * 8 + tig * 2;
            float bv0 = (n < 2048) ? b1[n] : b2[n - 2048];
            float bv1 = (n + 1 < 2048) ? b1[n + 1] : b2[n + 1 - 2048];
            int m = m0 + wm + mt * 16 + g;
            float2 v0 = {acc[mt][nt][0] + bv0, acc[mt][nt][1] + bv1};
            float2 v1 = {acc[mt][nt][2] + bv0, acc[mt][nt][3] + bv1};
            *(float2*)&g_XP[(size_t)m * N3 + n] = v0;
            *(float2*)&g_XP[(size_t)(m + 8) * N3 + n] = v1;
        }
    }
}

// ------------------------- phase 2: tensor-core recurrence ------------------
// Block b: K-half kh = b&1 (512 k), n-slice nb = (b>>1)*48.
// 8 warps: wm = (wid&3)*16, wng = (wid>>2)*24. Warp: m16 x 24 cols.
// smem: Bs hi/lo [48][520] resident (99840 B) + h chunk ring [2][hi|lo][64][136]
//       (69632 B) + bias (96 B).
#define BS_STR  520
#define HT_STR  136
#define R_BS    (48 * BS_STR)               // elems per Bs array
#define R_HT    (64 * HT_STR)               // elems per h array
#define R_HBUF  (2 * R_HT)                  // one ring buffer (hi + lo)
#define RSMEM   ((2 * R_BS + 2 * R_HBUF) * 2 + 128)

__device__ __forceinline__ void grid_sync() {
    __syncthreads();
    if (threadIdx.x == 0) {
        unsigned gen = g_bar_gen;
        __threadfence();
        if (atomicAdd(&g_bar_cnt, 1u) == NB - 1) {
            g_bar_cnt = 0;
            __threadfence();
            g_bar_gen = gen + 1;
        } else {
            while (g_bar_gen == gen) { __nanosleep(32); }
        }
        __threadfence();
    }
    __syncthreads();
}

__global__ __launch_bounds__(256, 1) void recurrence(
        const float* __restrict__ b1, const float* __restrict__ b2,
        float* __restrict__ out) {
    extern __shared__ __nv_bfloat16 rsm[];
    __nv_bfloat16* Bs_hi = rsm;                    // [48][520]
    __nv_bfloat16* Bs_lo = Bs_hi + R_BS;
    __nv_bfloat16* hring = Bs_lo + R_BS;           // [2][hi|lo][64][136]
    float* bias_s = (float*)(hring + 2 * R_HBUF);  // [24]

    const int tid = threadIdx.x;
    const int blk = blockIdx.x;
    const int wid = tid >> 5, lane = tid & 31;
    const int kh = blk & 1, ks = kh * 512;
    const int nb = (blk >> 1) * 48;
    const int gc0 = blk * 8;
    const int wm  = (wid & 3) * 16;
    const int wng = (wid >> 2) * 24;

    // ---- resident B slice (hi/lo) ------------------------------------------
#pragma unroll
    for (int j = 0; j < 12; j++) {
        int l = tid + j * 256;               // 0..3071
        int row = l >> 6, seg = l & 63;
        cp16(Bs_hi + row * BS_STR + seg * 8, g_Bhi + (size_t)(nb + row) * Kd + ks + seg * 8);
        cp16(Bs_lo + row * BS_STR + seg * 8, g_Blo + (size_t)(nb + row) * Kd + ks + seg * 8);
    }
    cp_commit();
    if (tid < 24) {
        int p = tid >> 3, ii = tid & 7, n = gc0 + ii;
        bias_s[tid] = (p == 0) ? b1[n] : (p == 1) ? b1[1024 + n] : b2[n];
    }
    cp_wait<0>();
    __syncthreads();

    const int arow  = lane & 15;
    const int akoff = (lane >> 4) << 3;
    const int brow  = (lane & 7) + ((lane >> 4) << 3);
    const int bkoff = ((lane >> 3) & 1) << 3;
    const int brow2 = lane & 7;
    const int bkoff2 = ((lane >> 3) & 1) << 3;
    const int g = lane >> 2, tig = lane & 3;

    const int um = tid & 63;                 // update element (m)
    const int ui = tid >> 6;                 // update gate-col 0..3 (e-loop adds 4)

    for (int t = 0; t < Tt; t++) {
        // issue one 128-k h chunk into ring buffer rb
        auto hissue = [&](int c, int rb) {
            __nv_bfloat16* d_hi = hring + rb * R_HBUF;
            __nv_bfloat16* d_lo = d_hi + R_HT;
#pragma unroll
            for (int j = 0; j < 4; j++) {
                int l = tid + j * 256;       // 0..1023
                int row = l >> 4, seg = l & 15;
                size_t src = (size_t)row * Kd + ks + c * 128 + seg * 8;
                cp16(d_hi + row * HT_STR + seg * 8, g_Hhi + src);
                cp16(d_lo + row * HT_STR + seg * 8, g_Hlo + src);
            }
            cp_commit();
        };

        // prefetch gating inputs (consumed after barrier A)
        float xq[2][3], hp[2];
#pragma unroll
        for (int e = 0; e < 2; e++) {
            int m = um, i = ui + e * 4, n = gc0 + i;
            const float* xp = g_XP + ((size_t)(m * Tt + t)) * N3 + n;
            xq[e][0] = xp[0]; xq[e][1] = xp[1024]; xq[e][2] = xp[2048];
            hp[e] = g_Hf[n * 64 + m];
        }

        float acc[3][4];
#pragma unroll
        for (int nt = 0; nt < 3; nt++)
#pragma unroll
            for (int i = 0; i < 4; i++) acc[nt][i] = 0.f;

        hissue(0, 0);
        for (int c = 0; c < 4; c++) {
            if (c < 3) { hissue(c + 1, (c + 1) & 1); cp_wait<1>(); }
            else       { cp_wait<0>(); }
            __syncthreads();

            __nv_bfloat16* hA_hi = hring + (c & 1) * R_HBUF;
            __nv_bfloat16* hA_lo = hA_hi + R_HT;
            const int ck = c * 128;

#pragma unroll
            for (int q = 0; q < 8; q++) {
                const int kk = q * 16;
                uint32_t ah[4], al[4], bh[4], bh2[2], bl[4], bl2[2];
                uint32_t ad = smem_u32(hA_hi + (wm + arow) * HT_STR + kk + akoff);
                ldsm4(ah, ad);
                ldsm4(al, smem_u32(hA_lo + (wm + arow) * HT_STR + kk + akoff));
                ldsm4(bh,  smem_u32(Bs_hi + (wng + brow) * BS_STR + ck + kk + bkoff));
                ldsm2(bh2, smem_u32(Bs_hi + (wng + 16 + brow2) * BS_STR + ck + kk + bkoff2));
                ldsm4(bl,  smem_u32(Bs_lo + (wng + brow) * BS_STR + ck + kk + bkoff));
                ldsm2(bl2, smem_u32(Bs_lo + (wng + 16 + brow2) * BS_STR + ck + kk + bkoff2));
                mma_bf16(acc[0], ah, &bh[0]);
                mma_bf16(acc[1], ah, &bh[2]);
                mma_bf16(acc[2], ah, bh2);
                mma_bf16(acc[0], al, &bh[0]);
                mma_bf16(acc[1], al, &bh[2]);
                mma_bf16(acc[2], al, bh2);
                mma_bf16(acc[0], ah, &bl[0]);
                mma_bf16(acc[1], ah, &bl[2]);
                mma_bf16(acc[2], ah, bl2);
            }
            __syncthreads();
        }

        // store split-K partials
#pragma unroll
        for (int nt = 0; nt < 3; nt++) {
            int n = nb + wng + nt * 8 + tig * 2;
            float* gp0 = g_G + ((size_t)(kh * 64 + wm + g)) * N3 + n;
            float* gp1 = g_G + ((size_t)(kh * 64 + wm + g + 8)) * N3 + n;
            *(float2*)gp0 = make_float2(acc[nt][0], acc[nt][1]);
            *(float2*)gp1 = make_float2(acc[nt][2], acc[nt][3]);
        }

        __threadfence();
        grid_sync();   // barrier A: partials visible; GEMM reads of h done

        // fused reduce + gates + h update (in-place)
#pragma unroll
        for (int e = 0; e < 2; e++) {
            int m = um, i = ui + e * 4, n = gc0 + i;
            float s1 = g_G[(size_t)m * N3 + n]        + g_G[(size_t)(64 + m) * N3 + n];
            float s2 = g_G[(size_t)m * N3 + 1024 + n] + g_G[(size_t)(64 + m) * N3 + 1024 + n];
            float sh = g_G[(size_t)m * N3 + 2048 + n] + g_G[(size_t)(64 + m) * N3 + 2048 + n];
            // reference adds biases in BOTH x-proj and h-proj — replicate
            float z = 1.f / (1.f + expf(-(xq[e][0] + s1 + bias_s[i])));
            float r = 1.f / (1.f + expf(-(xq[e][1] + s2 + bias_s[8 + i])));
            float hrec = sh + bias_s[16 + i];
            float hn = z * hp[e] + (1.f - z) * tanhf(xq[e][2] + r * hrec);
            g_Hf[n * 64 + m] = hn;
            __nv_bfloat16 hhi = __float2bfloat16(hn);
            __nv_bfloat16 hlo = __float2bfloat16(hn - __bfloat162float(hhi));
            g_Hhi[m * Nn + n] = hhi;
            g_Hlo[m * Nn + n] = hlo;
            if (t == Tt - 1) out[m * Nn + n] = hn;
        }

        __threadfence();
        grid_sync();   // barrier B: new h visible for next step's GEMM
    }
}

// ---------------------------------------------------------------------------
extern "C" void kernel_launch(void* const* d_in, const int* in_sizes, int n_in,
                              void* d_out, int out_size) {
    const float *fx = nullptr, *W1 = nullptr, *b1 = nullptr, *W2 = nullptr, *b2 = nullptr;
    for (int i = 0; i < n_in; i++) {
        switch (in_sizes[i]) {
            case Bsz * Nn * Tt:  fx = (const float*)d_in[i]; break;
            case Nn * 2 * Nn:    W1 = (const float*)d_in[i]; break;
            case 2 * Nn:         b1 = (const float*)d_in[i]; break;
            case Nn * Nn:        W2 = (const float*)d_in[i]; break;
            case Nn:             b2 = (const float*)d_in[i]; break;
            default: break;
        }
    }
    float* out = (float*)d_out;

    cudaFuncSetAttribute(xproj_mma,  cudaFuncAttributeMaxDynamicSharedMemorySize, XSMEM);
    cudaFuncSetAttribute(recurrence, cudaFuncAttributeMaxDynamicSharedMemorySize, RSMEM);

    init_state<<<(Nn * Bsz + 255) / 256, 256>>>();

    conv_a<<<dim3(Kd / 32, Tt / 32, Bsz), 256>>>(fx);
    conv_w<<<dim3(Kd / 32, N3 / 32), 256>>>(W1, W2);

    xproj_mma<<<dim3(N3 / 128, Mrows / 128), 256, XSMEM>>>(b1, b2);

    recurrence<<<NB, 256, RSMEM>>>(b1, b2, out);
}

// round 16
// speedup vs baseline: 1.7533x; 1.2072x over previous
#include <cuda_runtime.h>
#include <cuda_bf16.h>
#include <cstdint>
#include <cstddef>

// ---------------------------------------------------------------------------
// GRU (B=64, N=1024, T=512) — both GEMMs on the tensor pipe via mma.sync
// (m16n8k16 bf16, bf16x3 split: Ah*Bh + Al*Bh + Ah*Bl, fp32 accumulate).
//
// Phase 1:  XP = x @ [W1|W2] + [b1|b2]  (validated R13 kernel, ~1.56 ms).
// Phase 2:  persistent kernel, 512 steps, ONE grid barrier per step:
//   - 128 blocks; block owns 8 gate-cols = 24 GEMM cols (n, 1024+n, 2048+n),
//     FULL K=1024. B slice (bf16 hi/lo) resident in smem (97 KB).
//   - 8 warps = 4 m-tiles x 2-way in-block K-split; h chunks of 128 k,
//     cp.async double-buffered (R14 inner pattern).
//   - partials reduced in SMEM; update block-local; h double-buffered in
//     global (fp32 [n][m] + bf16 hi/lo [m][k]).
// ---------------------------------------------------------------------------

#define Bsz 64
#define Nn  1024
#define Tt  512
#define N3  3072
#define Kd  1024
#define NB  128
#define Mrows (Bsz * Tt)   // 32768

__device__ __forceinline__ void cp16(void* s, const void* g) {
    unsigned sa = (unsigned)__cvta_generic_to_shared(s);
    asm volatile("cp.async.ca.shared.global [%0], [%1], 16;" :: "r"(sa), "l"(g));
}
__device__ __forceinline__ void cp_commit() { asm volatile("cp.async.commit_group;"); }
template <int N>
__device__ __forceinline__ void cp_wait() {
    asm volatile("cp.async.wait_group %0;" :: "n"(N));
}
__device__ __forceinline__ uint32_t smem_u32(const void* p) {
    return (uint32_t)__cvta_generic_to_shared(p);
}
__device__ __forceinline__ void ldsm4(uint32_t* r, uint32_t addr) {
    asm volatile("ldmatrix.sync.aligned.m8n8.x4.shared.b16 {%0,%1,%2,%3}, [%4];"
                 : "=r"(r[0]), "=r"(r[1]), "=r"(r[2]), "=r"(r[3]) : "r"(addr));
}
__device__ __forceinline__ void ldsm2(uint32_t* r, uint32_t addr) {
    asm volatile("ldmatrix.sync.aligned.m8n8.x2.shared.b16 {%0,%1}, [%2];"
                 : "=r"(r[0]), "=r"(r[1]) : "r"(addr));
}
__device__ __forceinline__ void mma_bf16(float* c, const uint32_t* a, const uint32_t* b) {
    asm volatile(
        "mma.sync.aligned.m16n8k16.row.col.f32.bf16.bf16.f32 "
        "{%0,%1,%2,%3}, {%4,%5,%6,%7}, {%8,%9}, {%0,%1,%2,%3};"
        : "+f"(c[0]), "+f"(c[1]), "+f"(c[2]), "+f"(c[3])
        : "r"(a[0]), "r"(a[1]), "r"(a[2]), "r"(a[3]), "r"(b[0]), "r"(b[1]));
}

// ------------------------- device scratch ----------------------------------
__device__ float g_XP[(size_t)Mrows * N3];               // 402 MB
__device__ __nv_bfloat16 g_Ahi[(size_t)Mrows * Kd];      // [m][k]
__device__ __nv_bfloat16 g_Alo[(size_t)Mrows * Kd];
__device__ __nv_bfloat16 g_Bhi[(size_t)N3 * Kd];         // [n][k] = W^T
__device__ __nv_bfloat16 g_Blo[(size_t)N3 * Kd];
__device__ float g_Hf[2][Nn * Bsz];                      // fp32 h, [n][m]
__device__ __nv_bfloat16 g_Hhi[2][Bsz * Nn];             // bf16 h hi, [m][k]
__device__ __nv_bfloat16 g_Hlo[2][Bsz * Nn];             // bf16 h lo, [m][k]

__device__ volatile unsigned g_bar_gen;
__device__ unsigned g_bar_cnt;

__global__ void init_state() {
    int i = blockIdx.x * 256 + threadIdx.x;
    if (i < Nn * Bsz) {
        g_Hf[0][i] = 0.f;
        g_Hhi[0][i] = __float2bfloat16(0.f);
        g_Hlo[0][i] = __float2bfloat16(0.f);
    }
    if (i == 0) { g_bar_cnt = 0; g_bar_gen = 0; }
}

// ------------------------- converts ----------------------------------------
__global__ void conv_a(const float* __restrict__ fx) {
    __shared__ float tile[32][33];
    int k0 = blockIdx.x * 32, t0 = blockIdx.y * 32, b = blockIdx.z;
    int tx = threadIdx.x & 31, ty = threadIdx.x >> 5;
#pragma unroll
    for (int i = 0; i < 4; i++)
        tile[ty + 8 * i][tx] = fx[((size_t)b * Kd + k0 + ty + 8 * i) * Tt + t0 + tx];
    __syncthreads();
#pragma unroll
    for (int i = 0; i < 4; i++) {
        float v = tile[tx][ty + 8 * i];
        __nv_bfloat16 hi = __float2bfloat16(v);
        __nv_bfloat16 lo = __float2bfloat16(v - __bfloat162float(hi));
        size_t idx = ((size_t)b * Tt + t0 + ty + 8 * i) * Kd + k0 + tx;
        g_Ahi[idx] = hi;
        g_Alo[idx] = lo;
    }
}

__global__ void conv_w(const float* __restrict__ W1, const float* __restrict__ W2) {
    __shared__ float tile[32][33];
    int k0 = blockIdx.x * 32, n0 = blockIdx.y * 32;
    int tx = threadIdx.x & 31, ty = threadIdx.x >> 5;
    const float* src; int stride, nb;
    if (n0 < 2048) { src = W1; stride = 2048; nb = n0; }
    else           { src = W2; stride = 1024; nb = n0 - 2048; }
#pragma unroll
    for (int i = 0; i < 4; i++)
        tile[ty + 8 * i][tx] = src[(size_t)(k0 + ty + 8 * i) * stride + nb + tx];
    __syncthreads();
#pragma unroll
    for (int i = 0; i < 4; i++) {
        float v = tile[tx][ty + 8 * i];
        __nv_bfloat16 hi = __float2bfloat16(v);
        __nv_bfloat16 lo = __float2bfloat16(v - __bfloat162float(hi));
        size_t idx = (size_t)(n0 + ty + 8 * i) * Kd + k0 + tx;
        g_Bhi[idx] = hi;
        g_Blo[idx] = lo;
    }
}

// ------------------------- phase 1: mma.sync xproj (R13, unchanged) ---------
#define XR       40
#define XARR     (128 * XR)
#define XBUF     (4 * XARR)
#define XSMEM    (2 * XBUF * 2)

__global__ __launch_bounds__(256, 2) void xproj_mma(
        const float* __restrict__ b1, const float* __restrict__ b2) {
    extern __shared__ __nv_bfloat16 xsm[];

    const int tid = threadIdx.x;
    const int wid = tid >> 5, lane = tid & 31;
    const int n0 = blockIdx.x * 128;
    const int m0 = blockIdx.y * 128;
    const int wm = (wid & 3) * 32;
    const int wn = (wid >> 2) * 64;

    auto issue = [&](int c, int buf) {
        __nv_bfloat16* base = xsm + buf * XBUF;
#pragma unroll
        for (int j = 0; j < 8; j++) {
            int l = tid + j * 256;
            int arr = l >> 9;
            int r   = (l >> 2) & 127;
            int seg = l & 3;
            const __nv_bfloat16* gsrc;
            if (arr == 0)      gsrc = g_Ahi + (size_t)(m0 + r) * Kd + c * 32 + seg * 8;
            else if (arr == 1) gsrc = g_Alo + (size_t)(m0 + r) * Kd + c * 32 + seg * 8;
            else if (arr == 2) gsrc = g_Bhi + (size_t)(n0 + r) * Kd + c * 32 + seg * 8;
            else               gsrc = g_Blo + (size_t)(n0 + r) * Kd + c * 32 + seg * 8;
            cp16(base + arr * XARR + r * XR + seg * 8, gsrc);
        }
        cp_commit();
    };

    float acc[2][8][4];
#pragma unroll
    for (int mt = 0; mt < 2; mt++)
#pragma unroll
        for (int nt = 0; nt < 8; nt++)
#pragma unroll
            for (int i = 0; i < 4; i++) acc[mt][nt][i] = 0.f;

    issue(0, 0);
    int buf = 0;
    for (int c = 0; c < Kd / 32; c++) {
        const bool more = (c + 1 < Kd / 32);
        if (more) { issue(c + 1, buf ^ 1); cp_wait<1>(); }
        else      { cp_wait<0>(); }
        __syncthreads();

        __nv_bfloat16* bp = xsm + buf * XBUF;
        const int arow  = lane & 15;
        const int akoff = (lane >> 4) << 3;
        const int brow  = (lane & 7) + ((lane >> 4) << 3);
        const int bkoff = ((lane >> 3) & 1) << 3;

#pragma unroll
        for (int kk = 0; kk < 32; kk += 16) {
            uint32_t ah[2][4], al[2][4], bb[4][4];
#pragma unroll
            for (int mt = 0; mt < 2; mt++) {
                uint32_t ad = smem_u32(bp + (wm + mt * 16 + arow) * XR + kk + akoff);
                ldsm4(ah[mt], ad);
                ldsm4(al[mt], ad + XARR * 2);
            }
#pragma unroll
            for (int nt = 0; nt < 4; nt++) {
                uint32_t bd = smem_u32(bp + 2 * XARR + (wn + nt * 16 + brow) * XR + kk + bkoff);
                ldsm4(bb[nt], bd);
            }
#pragma unroll
            for (int mt = 0; mt < 2; mt++)
#pragma unroll
                for (int nt = 0; nt < 4; nt++) {
                    mma_bf16(acc[mt][nt * 2],     ah[mt], &bb[nt][0]);
                    mma_bf16(acc[mt][nt * 2 + 1], ah[mt], &bb[nt][2]);
                    mma_bf16(acc[mt][nt * 2],     al[mt], &bb[nt][0]);
                    mma_bf16(acc[mt][nt * 2 + 1], al[mt], &bb[nt][2]);
                }
#pragma unroll
            for (int nt = 0; nt < 4; nt++) {
                uint32_t bd = smem_u32(bp + 3 * XARR + (wn + nt * 16 + brow) * XR + kk + bkoff);
                ldsm4(bb[nt], bd);
            }
#pragma unroll
            for (int mt = 0; mt < 2; mt++)
#pragma unroll
                for (int nt = 0; nt < 4; nt++) {
                    mma_bf16(acc[mt][nt * 2],     ah[mt], &bb[nt][0]);
                    mma_bf16(acc[mt][nt * 2 + 1], ah[mt], &bb[nt][2]);
                }
        }
        __syncthreads();
        buf ^= 1;
    }

    const int g = lane >> 2, tig = lane & 3;
#pragma unroll
    for (int mt = 0; mt < 2; mt++) {
#pragma unroll
        for (int nt = 0; nt < 8; nt++) {
            int n = n0 + wn + nt * 8 + tig * 2;
            float bv0 = (n < 2048) ? b1[n] : b2[n - 2048];
            float bv1 = (n + 1 < 2048) ? b1[n + 1] : b2[n + 1 - 2048];
            int m = m0 + wm + mt * 16 + g;
            float2 v0 = {acc[mt][nt][0] + bv0, acc[mt][nt][1] + bv1};
            float2 v1 = {acc[mt][nt][2] + bv0, acc[mt][nt][3] + bv1};
            *(float2*)&g_XP[(size_t)m * N3 + n] = v0;
            *(float2*)&g_XP[(size_t)(m + 8) * N3 + n] = v1;
        }
    }
}

// ------------------------- phase 2: tensor-core recurrence ------------------
// Block owns 8 gate-cols gc0=blk*8 -> 24 GEMM cols, full K=1024.
// 8 warps: wm=(wid&3)*16, khw=wid>>2 (in-block k-split of 64 within each chunk).
// smem: Bs hi/lo [24][1032] resident; h ring [2][hi|lo][64][136]; p_s[2][64][26].
#define BS_STR  1032
#define HT_STR  136
#define R_BS    (24 * BS_STR)
#define R_HT    (64 * HT_STR)
#define R_HBUF  (2 * R_HT)
#define R_PS    (2 * 64 * 26)
#define RSMEM   ((2 * R_BS + 2 * R_HBUF) * 2 + R_PS * 4 + 128)

__device__ __forceinline__ void grid_sync() {
    __syncthreads();
    if (threadIdx.x == 0) {
        unsigned gen = g_bar_gen;
        __threadfence();
        if (atomicAdd(&g_bar_cnt, 1u) == NB - 1) {
            g_bar_cnt = 0;
            __threadfence();
            g_bar_gen = gen + 1;
        } else {
            while (g_bar_gen == gen) { __nanosleep(32); }
        }
        __threadfence();
    }
    __syncthreads();
}

__global__ __launch_bounds__(256, 1) void recurrence(
        const float* __restrict__ b1, const float* __restrict__ b2,
        float* __restrict__ out) {
    extern __shared__ __nv_bfloat16 rsm[];
    __nv_bfloat16* Bs_hi = rsm;                       // [24][1032]
    __nv_bfloat16* Bs_lo = Bs_hi + R_BS;
    __nv_bfloat16* hring = Bs_lo + R_BS;              // [2][hi|lo][64][136]
    float* p_s    = (float*)(hring + 2 * R_HBUF);     // [2][64][26]
    float* bias_s = p_s + R_PS;                       // [24]

    const int tid = threadIdx.x;
    const int blk = blockIdx.x;
    const int wid = tid >> 5, lane = tid & 31;
    const int gc0 = blk * 8;
    const int wm  = (wid & 3) * 16;
    const int khw = wid >> 2;                         // in-chunk k-split 0..1

    // ---- resident B slice: 24 rows (gc0+i, 1024+gc0+i, 2048+gc0+i) ---------
#pragma unroll
    for (int j = 0; j < 24; j++) {
        int l = tid + j * 256;                        // 0..6143 over hi+lo
        int arr = l >= 3072;                          // 0: hi, 1: lo
        int l2 = l - arr * 3072;
        int row = l2 >> 7, seg = l2 & 127;            // 24 rows x 128 float4-segs
        int p = row >> 3, ii = row & 7;
        int n = p * 1024 + gc0 + ii;
        const __nv_bfloat16* gsrc = (arr ? g_Blo : g_Bhi) + (size_t)n * Kd + seg * 8;
        __nv_bfloat16* dst = (arr ? Bs_lo : Bs_hi) + row * BS_STR + seg * 8;
        cp16(dst, gsrc);
    }
    cp_commit();
    if (tid < 24) {
        int p = tid >> 3, ii = tid & 7, n = gc0 + ii;
        bias_s[tid] = (p == 0) ? b1[n] : (p == 1) ? b1[1024 + n] : b2[n];
    }
    cp_wait<0>();
    __syncthreads();

    const int arow  = lane & 15;
    const int akoff = (lane >> 4) << 3;
    const int brow  = (lane & 7) + ((lane >> 4) << 3);
    const int bkoff = ((lane >> 3) & 1) << 3;
    const int brow2 = lane & 7;
    const int g = lane >> 2, tig = lane & 3;

    const int um = tid & 63;                          // update row (batch m)
    const int ui = tid >> 6;                          // update gate-col 0..3

    for (int t = 0; t < Tt; t++) {
        const __nv_bfloat16* hhi_c = g_Hhi[t & 1];
        const __nv_bfloat16* hlo_c = g_Hlo[t & 1];
        const float* hf_c = g_Hf[t & 1];

        // issue one 128-k h chunk into ring buffer rb
        auto hissue = [&](int c, int rb) {
            __nv_bfloat16* d_hi = hring + rb * R_HBUF;
            __nv_bfloat16* d_lo = d_hi + R_HT;
#pragma unroll
            for (int j = 0; j < 4; j++) {
                int l = tid + j * 256;                // 0..1023
                int row = l >> 4, seg = l & 15;
                size_t src = (size_t)row * Kd + c * 128 + seg * 8;
                cp16(d_hi + row * HT_STR + seg * 8, hhi_c + src);
                cp16(d_lo + row * HT_STR + seg * 8, hlo_c + src);
            }
            cp_commit();
        };

        // prefetch gating inputs
        float xq[2][3], hp[2];
#pragma unroll
        for (int e = 0; e < 2; e++) {
            int m = um, i = ui + e * 4, n = gc0 + i;
            const float* xp = g_XP + ((size_t)(m * Tt + t)) * N3 + n;
            xq[e][0] = xp[0]; xq[e][1] = xp[1024]; xq[e][2] = xp[2048];
            hp[e] = hf_c[n * 64 + m];
        }

        float acc[3][4];
#pragma unroll
        for (int nt = 0; nt < 3; nt++)
#pragma unroll
            for (int i = 0; i < 4; i++) acc[nt][i] = 0.f;

        hissue(0, 0);
        for (int c = 0; c < 8; c++) {
            if (c < 7) { hissue(c + 1, (c + 1) & 1); cp_wait<1>(); }
            else       { cp_wait<0>(); }
            __syncthreads();

            __nv_bfloat16* hA_hi = hring + (c & 1) * R_HBUF;
            __nv_bfloat16* hA_lo = hA_hi + R_HT;
            const int ck = c * 128 + khw * 64;        // warp's 64-k slice base (k within chunk row: khw*64)
            const int cks = khw * 64;                 // offset inside the chunk tile

#pragma unroll
            for (int q = 0; q < 4; q++) {
                const int kk = cks + q * 16;          // within HT_STR row
                uint32_t ah[4], al[4], bh[4], bh2[2], bl[4], bl2[2];
                uint32_t ad = smem_u32(hA_hi + (wm + arow) * HT_STR + kk + akoff);
                ldsm4(ah, ad);
                ldsm4(al, smem_u32(hA_lo + (wm + arow) * HT_STR + kk + akoff));
                const int bk = c * 128 + kk;          // k offset in resident B rows
                ldsm4(bh,  smem_u32(Bs_hi + brow * BS_STR + bk + bkoff));
                ldsm2(bh2, smem_u32(Bs_hi + (16 + brow2) * BS_STR + bk + bkoff));
                ldsm4(bl,  smem_u32(Bs_lo + brow * BS_STR + bk + bkoff));
                ldsm2(bl2, smem_u32(Bs_lo + (16 + brow2) * BS_STR + bk + bkoff));
                mma_bf16(acc[0], ah, &bh[0]);
                mma_bf16(acc[1], ah, &bh[2]);
                mma_bf16(acc[2], ah, bh2);
                mma_bf16(acc[0], al, &bh[0]);
                mma_bf16(acc[1], al, &bh[2]);
                mma_bf16(acc[2], al, bh2);
                mma_bf16(acc[0], ah, &bl[0]);
                mma_bf16(acc[1], ah, &bl[2]);
                mma_bf16(acc[2], ah, bl2);
            }
            __syncthreads();
        }

        // ---- partials to smem: p_s[khw][row][col] ---------------------------
#pragma unroll
        for (int nt = 0; nt < 3; nt++) {
            int col = nt * 8 + tig * 2;
            float* p0 = p_s + (khw * 64 + wm + g) * 26 + col;
            float* p1 = p_s + (khw * 64 + wm + g + 8) * 26 + col;
            *(float2*)p0 = make_float2(acc[nt][0], acc[nt][1]);
            *(float2*)p1 = make_float2(acc[nt][2], acc[nt][3]);
        }
        __syncthreads();

        // ---- fused reduce + gates + h update (block-local) ------------------
        float* hf_n = g_Hf[(t + 1) & 1];
        __nv_bfloat16* hhi_n = g_Hhi[(t + 1) & 1];
        __nv_bfloat16* hlo_n = g_Hlo[(t + 1) & 1];
#pragma unroll
        for (int e = 0; e < 2; e++) {
            int m = um, i = ui + e * 4, n = gc0 + i;
            float s1 = p_s[m * 26 + i]        + p_s[(64 + m) * 26 + i];
            float s2 = p_s[m * 26 + 8 + i]    + p_s[(64 + m) * 26 + 8 + i];
            float sh = p_s[m * 26 + 16 + i]   + p_s[(64 + m) * 26 + 16 + i];
            // reference adds biases in BOTH x-proj and h-proj — replicate
            float z = 1.f / (1.f + expf(-(xq[e][0] + s1 + bias_s[i])));
            float r = 1.f / (1.f + expf(-(xq[e][1] + s2 + bias_s[8 + i])));
            float hrec = sh + bias_s[16 + i];
            float hn = z * hp[e] + (1.f - z) * tanhf(xq[e][2] + r * hrec);
            hf_n[n * 64 + m] = hn;
            __nv_bfloat16 hhi = __float2bfloat16(hn);
            __nv_bfloat16 hlo = __float2bfloat16(hn - __bfloat162float(hhi));
            hhi_n[m * Nn + n] = hhi;
            hlo_n[m * Nn + n] = hlo;
            if (t == Tt - 1) out[m * Nn + n] = hn;
        }

        __threadfence();
        grid_sync();     // single barrier: new h visible before next step reads
    }
}

// ---------------------------------------------------------------------------
extern "C" void kernel_launch(void* const* d_in, const int* in_sizes, int n_in,
                              void* d_out, int out_size) {
    const float *fx = nullptr, *W1 = nullptr, *b1 = nullptr, *W2 = nullptr, *b2 = nullptr;
    for (int i = 0; i < n_in; i++) {
        switch (in_sizes[i]) {
            case Bsz * Nn * Tt:  fx = (const float*)d_in[i]; break;
            case Nn * 2 * Nn:    W1 = (const float*)d_in[i]; break;
            case 2 * Nn:         b1 = (const float*)d_in[i]; break;
            case Nn * Nn:        W2 = (const float*)d_in[i]; break;
            case Nn:             b2 = (const float*)d_in[i]; break;
            default: break;
        }
    }
    float* out = (float*)d_out;

    cudaFuncSetAttribute(xproj_mma,  cudaFuncAttributeMaxDynamicSharedMemorySize, XSMEM);
    cudaFuncSetAttribute(recurrence, cudaFuncAttributeMaxDynamicSharedMemorySize, RSMEM);

    init_state<<<(Nn * Bsz + 255) / 256, 256>>>();

    conv_a<<<dim3(Kd / 32, Tt / 32, Bsz), 256>>>(fx);
    conv_w<<<dim3(Kd / 32, N3 / 32), 256>>>(W1, W2);

    xproj_mma<<<dim3(N3 / 128, Mrows / 128), 256, XSMEM>>>(b1, b2);

    recurrence<<<NB, 256, RSMEM>>>(b1, b2, out);
}